// round 1
// baseline (speedup 1.0000x reference)
#include <cuda_runtime.h>
#include <cuda_bf16.h>
#include <math.h>

// Problem constants
#define S 2048
#define HID 2048
#define NH 16
#define NKV 4
#define HD 128
#define GRP (NH / NKV)
#define EPS 1e-6f

// Scratch (device globals; allocation is forbidden)
__device__ float g_qraw[S * HID];            // 16 MB
__device__ float g_kraw[S * (NKV * HD)];     // 4 MB
__device__ float g_vraw[S * (NKV * HD)];     // 4 MB
__device__ float g_q[NH * S * HD];           // 16 MB (head-major)
__device__ float g_k[NKV * S * HD];          // 4 MB  (head-major)
__device__ float g_s[(long long)NH * S * S]; // 256 MB scores/probs
__device__ float g_o[S * HID];               // 16 MB attention out [s, h*128+d]
__device__ float g_proj[S * HID];            // 16 MB pre-final-norm

// ---------------------------------------------------------------------------
// Tiled SGEMM: C[M,N] = A[M,K] * B (B either [K,N] or, if TRANS_B, [N,K]^T)
// BM=BN=64, BK=16, 256 threads, 4x4 accum per thread, float4 global ld/st.
// Per-head batching via blockIdx.z with strides; B head index = h / bDiv.
// CAUSAL_SKIP: skip tiles entirely above diagonal (scores).
// KCAP: limit K loop to m0+BM (PV after zero-filled softmax).
// ---------------------------------------------------------------------------
#define BM 64
#define BN 64
#define BK 16

template <bool TRANS_B, bool CAUSAL_SKIP, bool KCAP>
__global__ __launch_bounds__(256) void sgemm_kernel(
    int M, int N, int K,
    const float* __restrict__ A, int lda, long long strideA,
    const float* __restrict__ B, int ldb, long long strideB, int bDiv,
    float* __restrict__ C, int ldc, long long strideC)
{
    int h  = blockIdx.z;
    int m0 = blockIdx.y * BM;
    int n0 = blockIdx.x * BN;
    if (CAUSAL_SKIP && n0 > m0 + BM - 1) return;

    int Keff = K;
    if (KCAP) { int kc = m0 + BM; Keff = kc < K ? kc : K; }

    A += (long long)h * strideA;
    B += (long long)(h / bDiv) * strideB;
    C += (long long)h * strideC;

    __shared__ float As[BK][BM];
    __shared__ float Bs[BK][BN];

    int t  = threadIdx.x;
    int tx = t & 15;
    int ty = t >> 4;

    // A-tile (and TRANS_B B-tile) load pattern: 64 rows x 16 cols, float4/thread
    int ar = t >> 2;
    int ac = (t & 3) * 4;
    // NN B-tile load pattern: 16 rows x 64 cols, float4/thread
    int br = t >> 4;
    int bc = (t & 15) * 4;

    float acc[4][4];
#pragma unroll
    for (int i = 0; i < 4; i++)
#pragma unroll
        for (int j = 0; j < 4; j++) acc[i][j] = 0.0f;

    for (int k0 = 0; k0 < Keff; k0 += BK) {
        float4 av = *reinterpret_cast<const float4*>(
            A + (long long)(m0 + ar) * lda + k0 + ac);
        As[ac + 0][ar] = av.x;
        As[ac + 1][ar] = av.y;
        As[ac + 2][ar] = av.z;
        As[ac + 3][ar] = av.w;
        if (TRANS_B) {
            float4 bv = *reinterpret_cast<const float4*>(
                B + (long long)(n0 + ar) * ldb + k0 + ac);
            Bs[ac + 0][ar] = bv.x;
            Bs[ac + 1][ar] = bv.y;
            Bs[ac + 2][ar] = bv.z;
            Bs[ac + 3][ar] = bv.w;
        } else {
            float4 bv = *reinterpret_cast<const float4*>(
                B + (long long)(k0 + br) * ldb + n0 + bc);
            *reinterpret_cast<float4*>(&Bs[br][bc]) = bv;
        }
        __syncthreads();
#pragma unroll
        for (int kk = 0; kk < BK; kk++) {
            float4 a4 = *reinterpret_cast<const float4*>(&As[kk][ty * 4]);
            float4 b4 = *reinterpret_cast<const float4*>(&Bs[kk][tx * 4]);
            float av_[4] = {a4.x, a4.y, a4.z, a4.w};
            float bv_[4] = {b4.x, b4.y, b4.z, b4.w};
#pragma unroll
            for (int i = 0; i < 4; i++)
#pragma unroll
                for (int j = 0; j < 4; j++) acc[i][j] += av_[i] * bv_[j];
        }
        __syncthreads();
    }

#pragma unroll
    for (int i = 0; i < 4; i++) {
        float4 v = make_float4(acc[i][0], acc[i][1], acc[i][2], acc[i][3]);
        *reinterpret_cast<float4*>(
            C + (long long)(m0 + ty * 4 + i) * ldc + n0 + tx * 4) = v;
    }
}

// ---------------------------------------------------------------------------
// Per-head RMSNorm + RoPE, with transpose to head-major [h][s][d].
// blockIdx.x = s, blockIdx.y = head (0..15 Q, 16..19 K), 128 threads = d.
// ---------------------------------------------------------------------------
__global__ __launch_bounds__(128) void norm_rope_kernel(
    const float* __restrict__ qraw, const float* __restrict__ kraw,
    const float* __restrict__ cosT, const float* __restrict__ sinT,
    const float* __restrict__ qscale, const float* __restrict__ kscale,
    float* __restrict__ qout, float* __restrict__ kout)
{
    int s = blockIdx.x;
    int h = blockIdx.y;
    int d = threadIdx.x;

    const float* src;
    float* dst;
    const float* sc;
    if (h < NH) {
        src = qraw + (long long)s * HID + h * HD;
        dst = qout + ((long long)h * S + s) * HD;
        sc  = qscale;
    } else {
        int hk = h - NH;
        src = kraw + (long long)s * (NKV * HD) + hk * HD;
        dst = kout + ((long long)hk * S + s) * HD;
        sc  = kscale;
    }

    float x = src[d];
    float v = x * x;
#pragma unroll
    for (int o = 16; o > 0; o >>= 1) v += __shfl_xor_sync(0xffffffffu, v, o);
    __shared__ float red[4];
    if ((d & 31) == 0) red[d >> 5] = v;
    __syncthreads();
    float tot = red[0] + red[1] + red[2] + red[3];
    float r = rsqrtf(tot * (1.0f / HD) + EPS);

    __shared__ float xn[HD];
    float xv = x * r * sc[d];
    xn[d] = xv;
    __syncthreads();
    float other = (d < HD / 2) ? -xn[d + HD / 2] : xn[d - HD / 2];

    float c  = cosT[(long long)s * HD + d];
    float sn = sinT[(long long)s * HD + d];
    dst[d] = xv * c + other * sn;
}

// ---------------------------------------------------------------------------
// Causal softmax, in-place on scores. Zero-fills j > i so PV is a plain GEMM.
// blockIdx.x = row i, blockIdx.y = head, 256 threads.
// ---------------------------------------------------------------------------
__global__ __launch_bounds__(256) void softmax_kernel(float* __restrict__ sarr)
{
    int i = blockIdx.x;
    int h = blockIdx.y;
    float* row = sarr + ((long long)h * S + i) * S;
    int n = i + 1;
    const float scale = 0.08838834764831845f; // 1/sqrt(128)
    int t = threadIdx.x;

    float loc[8];
    float m = -INFINITY;
    int cnt = 0;
    for (int j = t; j < n; j += 256) {
        float v = row[j] * scale;
        loc[cnt++] = v;
        m = fmaxf(m, v);
    }

    __shared__ float red[8];
#pragma unroll
    for (int o = 16; o > 0; o >>= 1) m = fmaxf(m, __shfl_xor_sync(0xffffffffu, m, o));
    if ((t & 31) == 0) red[t >> 5] = m;
    __syncthreads();
    if (t == 0) {
        float v = red[0];
        for (int w = 1; w < 8; w++) v = fmaxf(v, red[w]);
        red[0] = v;
    }
    __syncthreads();
    m = red[0];
    __syncthreads();

    float ssum = 0.0f;
    for (int c = 0; c < cnt; c++) {
        float e = __expf(loc[c] - m);
        loc[c] = e;
        ssum += e;
    }
#pragma unroll
    for (int o = 16; o > 0; o >>= 1) ssum += __shfl_xor_sync(0xffffffffu, ssum, o);
    if ((t & 31) == 0) red[t >> 5] = ssum;
    __syncthreads();
    if (t == 0) {
        float v = 0.0f;
        for (int w = 0; w < 8; w++) v += red[w];
        red[0] = v;
    }
    __syncthreads();
    float inv = 1.0f / red[0];

    cnt = 0;
    for (int j = t; j < n; j += 256) row[j] = loc[cnt++] * inv;
    for (int j = n + t; j < S; j += 256) row[j] = 0.0f;
}

// ---------------------------------------------------------------------------
// Final RMSNorm over HID.
// ---------------------------------------------------------------------------
__global__ __launch_bounds__(256) void final_norm_kernel(
    const float* __restrict__ in, const float* __restrict__ scale,
    float* __restrict__ out)
{
    int s = blockIdx.x;
    int t = threadIdx.x;
    const float* row = in + (long long)s * HID;

    float loc[8];
    float ss = 0.0f;
#pragma unroll
    for (int c = 0; c < 8; c++) {
        float v = row[t + c * 256];
        loc[c] = v;
        ss += v * v;
    }
    __shared__ float red[8];
#pragma unroll
    for (int o = 16; o > 0; o >>= 1) ss += __shfl_xor_sync(0xffffffffu, ss, o);
    if ((t & 31) == 0) red[t >> 5] = ss;
    __syncthreads();
    if (t == 0) {
        float v = 0.0f;
        for (int w = 0; w < 8; w++) v += red[w];
        red[0] = v;
    }
    __syncthreads();
    float r = rsqrtf(red[0] * (1.0f / HID) + EPS);
#pragma unroll
    for (int c = 0; c < 8; c++)
        out[(long long)s * HID + t + c * 256] = loc[c] * r * scale[t + c * 256];
}

// ---------------------------------------------------------------------------
// Host launch
// ---------------------------------------------------------------------------
extern "C" void kernel_launch(void* const* d_in, const int* in_sizes, int n_in,
                              void* d_out, int out_size)
{
    const float* X   = (const float*)d_in[0];  // hidden_states [1,S,HID]
    const float* cosT = (const float*)d_in[1]; // [S,1,HD]
    const float* sinT = (const float*)d_in[2]; // [S,1,HD]
    const float* Wq  = (const float*)d_in[3];  // [HID, NH*HD]
    const float* Wk  = (const float*)d_in[4];  // [HID, NKV*HD]
    const float* Wv  = (const float*)d_in[5];  // [HID, NKV*HD]
    const float* Wo  = (const float*)d_in[6];  // [HID, HID]
    const float* qsc = (const float*)d_in[7];  // [HD]
    const float* ksc = (const float*)d_in[8];  // [HD]
    const float* lsc = (const float*)d_in[9];  // [HID]
    // d_in[10] attention_mask: known causal; unused.
    float* out = (float*)d_out;

    float *qraw, *kraw, *vraw, *q, *k, *sc, *o, *proj;
    cudaGetSymbolAddress((void**)&qraw, g_qraw);
    cudaGetSymbolAddress((void**)&kraw, g_kraw);
    cudaGetSymbolAddress((void**)&vraw, g_vraw);
    cudaGetSymbolAddress((void**)&q,    g_q);
    cudaGetSymbolAddress((void**)&k,    g_k);
    cudaGetSymbolAddress((void**)&sc,   g_s);
    cudaGetSymbolAddress((void**)&o,    g_o);
    cudaGetSymbolAddress((void**)&proj, g_proj);

    // 1-3. QKV projections
    sgemm_kernel<false, false, false><<<dim3(HID / BN, S / BM, 1), 256>>>(
        S, HID, HID, X, HID, 0, Wq, HID, 0, 1, qraw, HID, 0);
    sgemm_kernel<false, false, false><<<dim3((NKV * HD) / BN, S / BM, 1), 256>>>(
        S, NKV * HD, HID, X, HID, 0, Wk, NKV * HD, 0, 1, kraw, NKV * HD, 0);
    sgemm_kernel<false, false, false><<<dim3((NKV * HD) / BN, S / BM, 1), 256>>>(
        S, NKV * HD, HID, X, HID, 0, Wv, NKV * HD, 0, 1, vraw, NKV * HD, 0);

    // 4. Per-head RMSNorm + RoPE + transpose to head-major
    norm_rope_kernel<<<dim3(S, NH + NKV), 128>>>(qraw, kraw, cosT, sinT,
                                                 qsc, ksc, q, k);

    // 5. Scores: per Q-head, S x S = Q_h @ K_{h/4}^T, causal tile skip
    sgemm_kernel<true, true, false><<<dim3(S / BN, S / BM, NH), 256>>>(
        S, S, HD,
        q, HD, (long long)S * HD,
        k, HD, (long long)S * HD, GRP,
        sc, S, (long long)S * S);

    // 6. Causal softmax (zero-fills upper triangle)
    softmax_kernel<<<dim3(S, NH), 256>>>(sc);

    // 7. PV: per Q-head, [S,HD] = P_h @ V_{h/4}, K capped at diagonal
    sgemm_kernel<false, false, true><<<dim3(HD / BN, S / BM, NH), 256>>>(
        S, HD, S,
        sc, S, (long long)S * S,
        vraw, NKV * HD, HD, GRP,
        o, HID, HD);

    // 8. Output projection
    sgemm_kernel<false, false, false><<<dim3(HID / BN, S / BM, 1), 256>>>(
        S, HID, HID, o, HID, 0, Wo, HID, 0, 1, proj, HID, 0);

    // 9. Final RMSNorm
    final_norm_kernel<<<S, 256>>>(proj, lsc, out);
}

// round 3
// speedup vs baseline: 2.5310x; 2.5310x over previous
#include <cuda_runtime.h>
#include <cuda_bf16.h>
#include <math.h>
#include <stdint.h>

// Problem constants
#define S 2048
#define HID 2048
#define NH 16
#define NKV 4
#define HD 128
#define GRP (NH / NKV)
#define EPS 1e-6f
#define NQKV 3072  // NH*HD + 2*NKV*HD

typedef __nv_bfloat16 bf16;

// ---------------------------------------------------------------------------
// Scratch (device globals; allocation is forbidden)
// ---------------------------------------------------------------------------
__device__ float g_qkv[S * NQKV];                 // 24 MB  fused QKV proj out
__device__ bf16  g_xhi[S * HID], g_xlo[S * HID];  // 8+8 MB
__device__ bf16  g_wqkvT_hi[NQKV * HID], g_wqkvT_lo[NQKV * HID];  // 12+12 MB
__device__ bf16  g_woT_hi[HID * HID], g_woT_lo[HID * HID];        // 8+8 MB
__device__ bf16  g_qhi[NH * S * HD], g_qlo[NH * S * HD];          // 8+8 MB
__device__ bf16  g_khi[NKV * S * HD], g_klo[NKV * S * HD];        // 2+2 MB
__device__ bf16  g_vthi[NKV * HD * S], g_vtlo[NKV * HD * S];      // 2+2 MB
__device__ float g_s[(long long)NH * S * S];      // 256 MB scores
__device__ bf16  g_phi[(long long)NH * S * S];    // 128 MB probs hi
__device__ bf16  g_plo[(long long)NH * S * S];    // 128 MB probs lo
__device__ float g_o[S * HID];                    // 16 MB attention out fp32
__device__ bf16  g_ohi[S * HID], g_olo[S * HID];  // 4+4 MB
__device__ float g_proj[S * HID];                 // 16 MB pre-final-norm

// ---------------------------------------------------------------------------
// PTX helpers (portable: sm_80+ PTX, legal in compute_103)
// ---------------------------------------------------------------------------
__device__ __forceinline__ uint32_t smem_u32(const void* p) {
    uint32_t a;
    asm("{ .reg .u64 t; cvta.to.shared.u64 t, %1; cvt.u32.u64 %0, t; }"
        : "=r"(a) : "l"(p));
    return a;
}

#define CP_ASYNC16(dst, src) \
    asm volatile("cp.async.cg.shared.global [%0], [%1], 16;" \
        :: "r"(dst), "l"(src))
#define CP_COMMIT() asm volatile("cp.async.commit_group;" ::: "memory")
#define CP_WAIT0() asm volatile("cp.async.wait_group 0;" ::: "memory")
#define CP_WAIT1() asm volatile("cp.async.wait_group 1;" ::: "memory")

#define LDSM_X4(r0, r1, r2, r3, addr) \
    asm volatile("ldmatrix.sync.aligned.m8n8.x4.shared.b16 {%0,%1,%2,%3}, [%4];" \
        : "=r"(r0), "=r"(r1), "=r"(r2), "=r"(r3) : "r"(addr))

#define MMA_BF16(d, a, b0, b1) \
    asm volatile("mma.sync.aligned.m16n8k16.row.col.f32.bf16.bf16.f32 " \
        "{%0,%1,%2,%3}, {%4,%5,%6,%7}, {%8,%9}, {%0,%1,%2,%3};" \
        : "+f"((d)[0]), "+f"((d)[1]), "+f"((d)[2]), "+f"((d)[3]) \
        : "r"((a)[0]), "r"((a)[1]), "r"((a)[2]), "r"((a)[3]), \
          "r"(b0), "r"(b1))

__device__ __forceinline__ void split_bf16(float v, bf16& h, bf16& l) {
    h = __float2bfloat16(v);
    l = __float2bfloat16(v - __bfloat162float(h));
}

// ---------------------------------------------------------------------------
// Split-bf16 GEMM via mma.sync: C[M,N] = A[M,K] @ B[N,K]^T
// A,B given as (hi,lo) bf16 K-major. BM=BN=128, BK=64, 256 thr (8 warps,
// warp tile 32x64), 2-stage cp.async double buffer, swizzled 128B SMEM rows.
// 3 MMAs per fragment pair: Ahi*Bhi + Ahi*Blo + Alo*Bhi.
// ---------------------------------------------------------------------------
template <bool CAUSAL, bool KCAP>
__global__ __launch_bounds__(256, 1) void mma_gemm(
    int M, int N, int K,
    const bf16* __restrict__ Ahi, const bf16* __restrict__ Alo,
    int lda, long long sA,
    const bf16* __restrict__ Bhi, const bf16* __restrict__ Blo,
    int ldb, long long sB, int bdiv,
    float* __restrict__ C, int ldc, long long sC)
{
    constexpr int BM = 128, BN = 128, BK = 64;
    constexpr int TILE_B = BM * BK * 2;     // 16384 bytes per (hi|lo) subtile
    constexpr int STAGE = 4 * TILE_B;       // Ahi, Alo, Bhi, Blo

    const int h  = blockIdx.z;
    const int m0 = blockIdx.y * BM;
    const int n0 = blockIdx.x * BN;
    if (CAUSAL && n0 >= m0 + BM) return;

    int Keff = K;
    if (KCAP) { int kc = m0 + BM; Keff = kc < K ? kc : K; }
    const int nIter = Keff / BK;

    Ahi += (long long)h * sA;  Alo += (long long)h * sA;
    Bhi += (long long)(h / bdiv) * sB;  Blo += (long long)(h / bdiv) * sB;
    C   += (long long)h * sC;

    extern __shared__ char smem[];
    const uint32_t sbase = smem_u32(smem);

    const int tid  = threadIdx.x;
    const int wid  = tid >> 5;
    const int lane = tid & 31;
    const int wm   = wid >> 1;       // 0..3 -> m offset wm*32
    const int wn   = wid & 1;        // 0..1 -> n offset wn*64

    // cp.async loader: one stage = 4 subtiles x 1024 16B-chunks
    auto load_stage = [&](int st, int k0) {
        const uint32_t base = sbase + st * STAGE;
#pragma unroll
        for (int t = 0; t < 4; t++) {
            int idx = tid + t * 256;       // 0..1023
            int r = idx >> 3;
            int c = idx & 7;
            uint32_t soff = (uint32_t)(r * 128 + ((c ^ (r & 7)) << 4));
            long long ga = (long long)(m0 + r) * lda + k0 + c * 8;
            long long gb = (long long)(n0 + r) * ldb + k0 + c * 8;
            CP_ASYNC16(base + soff,              (const char*)(Ahi + ga));
            CP_ASYNC16(base + TILE_B + soff,     (const char*)(Alo + ga));
            CP_ASYNC16(base + 2 * TILE_B + soff, (const char*)(Bhi + gb));
            CP_ASYNC16(base + 3 * TILE_B + soff, (const char*)(Blo + gb));
        }
        CP_COMMIT();
    };

    // ldmatrix per-lane row precompute
    const int lrow = lane & 15;
    const int lsel = lane >> 4;
    int arow[2], brow[4];
#pragma unroll
    for (int mt = 0; mt < 2; mt++) arow[mt] = wm * 32 + mt * 16 + lrow;
#pragma unroll
    for (int g = 0; g < 4; g++)    brow[g] = wn * 64 + g * 16 + lrow;

    float acc[2][8][4];
#pragma unroll
    for (int mt = 0; mt < 2; mt++)
#pragma unroll
        for (int j = 0; j < 8; j++)
#pragma unroll
            for (int e = 0; e < 4; e++) acc[mt][j][e] = 0.0f;

    load_stage(0, 0);

    for (int it = 0; it < nIter; it++) {
        if (it + 1 < nIter) { load_stage((it + 1) & 1, (it + 1) * BK); CP_WAIT1(); }
        else                { CP_WAIT0(); }
        __syncthreads();

        const uint32_t base = sbase + (it & 1) * STAGE;
#pragma unroll
        for (int ks = 0; ks < 4; ks++) {
            const int chunk = ks * 2 + lsel;
            uint32_t ah[2][4], al[2][4], bh[4][4], bl[4][4];
#pragma unroll
            for (int mt = 0; mt < 2; mt++) {
                uint32_t off = (uint32_t)(arow[mt] * 128 +
                               ((chunk ^ (arow[mt] & 7)) << 4));
                LDSM_X4(ah[mt][0], ah[mt][1], ah[mt][2], ah[mt][3], base + off);
                LDSM_X4(al[mt][0], al[mt][1], al[mt][2], al[mt][3],
                        base + TILE_B + off);
            }
#pragma unroll
            for (int g = 0; g < 4; g++) {
                uint32_t off = (uint32_t)(brow[g] * 128 +
                               ((chunk ^ (brow[g] & 7)) << 4));
                LDSM_X4(bh[g][0], bh[g][1], bh[g][2], bh[g][3],
                        base + 2 * TILE_B + off);
                LDSM_X4(bl[g][0], bl[g][1], bl[g][2], bl[g][3],
                        base + 3 * TILE_B + off);
            }
#pragma unroll
            for (int mt = 0; mt < 2; mt++)
#pragma unroll
                for (int j = 0; j < 8; j++) {
                    int g = j >> 1, o = j & 1;
                    MMA_BF16(acc[mt][j], ah[mt], bh[g][o], bh[g][2 + o]);
                    MMA_BF16(acc[mt][j], ah[mt], bl[g][o], bl[g][2 + o]);
                    MMA_BF16(acc[mt][j], al[mt], bh[g][o], bh[g][2 + o]);
                }
        }
        __syncthreads();
    }

    // epilogue: fp32 stores (2 float2 per mma tile per lane)
    const int er = lane >> 2;
    const int ec = (lane & 3) * 2;
#pragma unroll
    for (int mt = 0; mt < 2; mt++) {
        int r0 = m0 + wm * 32 + mt * 16 + er;
#pragma unroll
        for (int j = 0; j < 8; j++) {
            int col = n0 + wn * 64 + j * 8 + ec;
            *reinterpret_cast<float2*>(C + (long long)r0 * ldc + col) =
                make_float2(acc[mt][j][0], acc[mt][j][1]);
            *reinterpret_cast<float2*>(C + (long long)(r0 + 8) * ldc + col) =
                make_float2(acc[mt][j][2], acc[mt][j][3]);
        }
    }
}

// ---------------------------------------------------------------------------
// Elementwise fp32 -> bf16 (hi, lo)
// ---------------------------------------------------------------------------
__global__ __launch_bounds__(256) void convert_kernel(
    const float* __restrict__ in, bf16* __restrict__ hi,
    bf16* __restrict__ lo, int n)
{
    int idx = blockIdx.x * 256 + threadIdx.x;
    if (idx < n) {
        bf16 h, l;
        split_bf16(in[idx], h, l);
        hi[idx] = h; lo[idx] = l;
    }
}

// ---------------------------------------------------------------------------
// Transpose + convert: out[c][r] = split(in[r][c]) for [R x C_] fp32 input.
// ---------------------------------------------------------------------------
__global__ __launch_bounds__(256) void transpose_conv_kernel(
    const float* __restrict__ in, int ldi, long long sIn,
    bf16* __restrict__ ohi, bf16* __restrict__ olo, int ldo, long long sOut)
{
    __shared__ float t[32][33];
    const float* ip = in + (long long)blockIdx.z * sIn;
    bf16* oh = ohi + (long long)blockIdx.z * sOut;
    bf16* ol = olo + (long long)blockIdx.z * sOut;
    int c0 = blockIdx.x * 32, r0 = blockIdx.y * 32;
    int x = threadIdx.x, y = threadIdx.y;  // 32 x 8
#pragma unroll
    for (int i = 0; i < 32; i += 8)
        t[y + i][x] = ip[(long long)(r0 + y + i) * ldi + c0 + x];
    __syncthreads();
#pragma unroll
    for (int i = 0; i < 32; i += 8) {
        bf16 h, l;
        split_bf16(t[x][y + i], h, l);
        long long o = (long long)(c0 + y + i) * ldo + r0 + x;
        oh[o] = h; ol[o] = l;
    }
}

// ---------------------------------------------------------------------------
// Per-head RMSNorm + RoPE from fused QKV buffer -> head-major bf16 hi/lo.
// blockIdx.y: 0..15 Q heads, 16..19 K heads. 128 threads = d.
// ---------------------------------------------------------------------------
__global__ __launch_bounds__(128) void norm_rope_kernel(
    const float* __restrict__ qkv,
    const float* __restrict__ cosT, const float* __restrict__ sinT,
    const float* __restrict__ qscale, const float* __restrict__ kscale,
    bf16* __restrict__ qhi, bf16* __restrict__ qlo,
    bf16* __restrict__ khi, bf16* __restrict__ klo)
{
    int s = blockIdx.x;
    int h = blockIdx.y;
    int d = threadIdx.x;

    const float* src;
    long long dsto;
    const float* sc;
    bf16 *dhi, *dlo;
    if (h < NH) {
        src  = qkv + (long long)s * NQKV + h * HD;
        dsto = ((long long)h * S + s) * HD;
        sc = qscale; dhi = qhi; dlo = qlo;
    } else {
        int hk = h - NH;
        src  = qkv + (long long)s * NQKV + HID + hk * HD;
        dsto = ((long long)hk * S + s) * HD;
        sc = kscale; dhi = khi; dlo = klo;
    }

    float x = src[d];
    float v = x * x;
#pragma unroll
    for (int o = 16; o > 0; o >>= 1) v += __shfl_xor_sync(0xffffffffu, v, o);
    __shared__ float red[4];
    if ((d & 31) == 0) red[d >> 5] = v;
    __syncthreads();
    float tot = red[0] + red[1] + red[2] + red[3];
    float r = rsqrtf(tot * (1.0f / HD) + EPS);

    __shared__ float xn[HD];
    float xv = x * r * sc[d];
    xn[d] = xv;
    __syncthreads();
    float other = (d < HD / 2) ? -xn[d + HD / 2] : xn[d - HD / 2];

    float c  = cosT[(long long)s * HD + d];
    float sn = sinT[(long long)s * HD + d];
    float outv = xv * c + other * sn;
    bf16 hh, ll;
    split_bf16(outv, hh, ll);
    dhi[dsto + d] = hh;
    dlo[dsto + d] = ll;
}

// ---------------------------------------------------------------------------
// Causal softmax: fp32 scores -> bf16 (hi, lo) probs; zero-fill to next
// 128-boundary only (PV never reads past it).
// ---------------------------------------------------------------------------
__global__ __launch_bounds__(256) void softmax_kernel(
    const float* __restrict__ sarr, bf16* __restrict__ phi,
    bf16* __restrict__ plo)
{
    int i = blockIdx.x;
    int h = blockIdx.y;
    long long ro = ((long long)h * S + i) * S;
    const float* row = sarr + ro;
    int n = i + 1;
    const float scale = 0.08838834764831845f;  // 1/sqrt(128)
    int t = threadIdx.x;

    float loc[8];
    float m = -INFINITY;
    int cnt = 0;
    for (int j = t; j < n; j += 256) {
        float v = row[j] * scale;
        loc[cnt++] = v;
        m = fmaxf(m, v);
    }

    __shared__ float red[8];
#pragma unroll
    for (int o = 16; o > 0; o >>= 1) m = fmaxf(m, __shfl_xor_sync(0xffffffffu, m, o));
    if ((t & 31) == 0) red[t >> 5] = m;
    __syncthreads();
    if (t == 0) {
        float v = red[0];
        for (int w = 1; w < 8; w++) v = fmaxf(v, red[w]);
        red[0] = v;
    }
    __syncthreads();
    m = red[0];
    __syncthreads();

    float ssum = 0.0f;
    for (int c = 0; c < cnt; c++) {
        float e = __expf(loc[c] - m);
        loc[c] = e;
        ssum += e;
    }
#pragma unroll
    for (int o = 16; o > 0; o >>= 1) ssum += __shfl_xor_sync(0xffffffffu, ssum, o);
    if ((t & 31) == 0) red[t >> 5] = ssum;
    __syncthreads();
    if (t == 0) {
        float v = 0.0f;
        for (int w = 0; w < 8; w++) v += red[w];
        red[0] = v;
    }
    __syncthreads();
    float inv = 1.0f / red[0];

    cnt = 0;
    for (int j = t; j < n; j += 256) {
        float p = loc[cnt++] * inv;
        bf16 hh, ll;
        split_bf16(p, hh, ll);
        phi[ro + j] = hh;
        plo[ro + j] = ll;
    }
    int fillEnd = ((i >> 7) + 1) << 7;  // next 128 boundary
    if (fillEnd > S) fillEnd = S;
    for (int j = n + t; j < fillEnd; j += 256) {
        phi[ro + j] = __float2bfloat16(0.0f);
        plo[ro + j] = __float2bfloat16(0.0f);
    }
}

// ---------------------------------------------------------------------------
// Final RMSNorm over HID.
// ---------------------------------------------------------------------------
__global__ __launch_bounds__(256) void final_norm_kernel(
    const float* __restrict__ in, const float* __restrict__ scale,
    float* __restrict__ out)
{
    int s = blockIdx.x;
    int t = threadIdx.x;
    const float* row = in + (long long)s * HID;

    float loc[8];
    float ss = 0.0f;
#pragma unroll
    for (int c = 0; c < 8; c++) {
        float v = row[t + c * 256];
        loc[c] = v;
        ss += v * v;
    }
    __shared__ float red[8];
#pragma unroll
    for (int o = 16; o > 0; o >>= 1) ss += __shfl_xor_sync(0xffffffffu, ss, o);
    if ((t & 31) == 0) red[t >> 5] = ss;
    __syncthreads();
    if (t == 0) {
        float v = 0.0f;
        for (int w = 0; w < 8; w++) v += red[w];
        red[0] = v;
    }
    __syncthreads();
    float r = rsqrtf(red[0] * (1.0f / HID) + EPS);
#pragma unroll
    for (int c = 0; c < 8; c++)
        out[(long long)s * HID + t + c * 256] = loc[c] * r * scale[t + c * 256];
}

// ---------------------------------------------------------------------------
// Host launch
// ---------------------------------------------------------------------------
extern "C" void kernel_launch(void* const* d_in, const int* in_sizes, int n_in,
                              void* d_out, int out_size)
{
    const float* X    = (const float*)d_in[0];
    const float* cosT = (const float*)d_in[1];
    const float* sinT = (const float*)d_in[2];
    const float* Wq   = (const float*)d_in[3];
    const float* Wk   = (const float*)d_in[4];
    const float* Wv   = (const float*)d_in[5];
    const float* Wo   = (const float*)d_in[6];
    const float* qsc  = (const float*)d_in[7];
    const float* ksc  = (const float*)d_in[8];
    const float* lsc  = (const float*)d_in[9];
    float* out = (float*)d_out;

    float *qkv, *sc, *o, *proj;
    bf16 *xhi, *xlo, *wqkvhi, *wqkvlo, *wohi, *wolo;
    bf16 *qhi, *qlo, *khi, *klo, *vthi, *vtlo, *phi, *plo, *ohi, *olo;
    cudaGetSymbolAddress((void**)&qkv,    g_qkv);
    cudaGetSymbolAddress((void**)&sc,     g_s);
    cudaGetSymbolAddress((void**)&o,      g_o);
    cudaGetSymbolAddress((void**)&proj,   g_proj);
    cudaGetSymbolAddress((void**)&xhi,    g_xhi);
    cudaGetSymbolAddress((void**)&xlo,    g_xlo);
    cudaGetSymbolAddress((void**)&wqkvhi, g_wqkvT_hi);
    cudaGetSymbolAddress((void**)&wqkvlo, g_wqkvT_lo);
    cudaGetSymbolAddress((void**)&wohi,   g_woT_hi);
    cudaGetSymbolAddress((void**)&wolo,   g_woT_lo);
    cudaGetSymbolAddress((void**)&qhi,    g_qhi);
    cudaGetSymbolAddress((void**)&qlo,    g_qlo);
    cudaGetSymbolAddress((void**)&khi,    g_khi);
    cudaGetSymbolAddress((void**)&klo,    g_klo);
    cudaGetSymbolAddress((void**)&vthi,   g_vthi);
    cudaGetSymbolAddress((void**)&vtlo,   g_vtlo);
    cudaGetSymbolAddress((void**)&phi,    g_phi);
    cudaGetSymbolAddress((void**)&plo,    g_plo);
    cudaGetSymbolAddress((void**)&ohi,    g_ohi);
    cudaGetSymbolAddress((void**)&olo,    g_olo);

    const int SMEM = 2 * 4 * 128 * 64 * 2;  // 131072
    cudaFuncSetAttribute(mma_gemm<false, false>,
                         cudaFuncAttributeMaxDynamicSharedMemorySize, SMEM);
    cudaFuncSetAttribute(mma_gemm<true, false>,
                         cudaFuncAttributeMaxDynamicSharedMemorySize, SMEM);
    cudaFuncSetAttribute(mma_gemm<false, true>,
                         cudaFuncAttributeMaxDynamicSharedMemorySize, SMEM);

    // 0a. X -> hi/lo
    convert_kernel<<<(S * HID) / 256, 256>>>(X, xhi, xlo, S * HID);
    // 0b. Weights: transpose+convert into fused [NQKV][HID] and Wo^T
    transpose_conv_kernel<<<dim3(HID / 32, HID / 32, 1), dim3(32, 8)>>>(
        Wq, HID, 0, wqkvhi, wqkvlo, HID, 0);
    transpose_conv_kernel<<<dim3((NKV * HD) / 32, HID / 32, 1), dim3(32, 8)>>>(
        Wk, NKV * HD, 0, wqkvhi + (long long)HID * HID,
        wqkvlo + (long long)HID * HID, HID, 0);
    transpose_conv_kernel<<<dim3((NKV * HD) / 32, HID / 32, 1), dim3(32, 8)>>>(
        Wv, NKV * HD, 0, wqkvhi + (long long)(HID + NKV * HD) * HID,
        wqkvlo + (long long)(HID + NKV * HD) * HID, HID, 0);
    transpose_conv_kernel<<<dim3(HID / 32, HID / 32, 1), dim3(32, 8)>>>(
        Wo, HID, 0, wohi, wolo, HID, 0);

    // 1. Fused QKV projection: [S, NQKV]
    mma_gemm<false, false><<<dim3(NQKV / 128, S / 128, 1), 256, SMEM>>>(
        S, NQKV, HID, xhi, xlo, HID, 0, wqkvhi, wqkvlo, HID, 0, 1,
        qkv, NQKV, 0);

    // 2. Per-head RMSNorm + RoPE -> head-major bf16 hi/lo
    norm_rope_kernel<<<dim3(S, NH + NKV), 128>>>(
        qkv, cosT, sinT, qsc, ksc, qhi, qlo, khi, klo);

    // 2b. V^T per kv head: [kv][d][s] bf16 hi/lo (from qkv cols 2560+)
    transpose_conv_kernel<<<dim3(HD / 32, S / 32, NKV), dim3(32, 8)>>>(
        qkv + HID + NKV * HD, NQKV, HD, vthi, vtlo, S, (long long)HD * S);

    // 3. Scores: per Q-head S x S, causal tile-skip
    mma_gemm<true, false><<<dim3(S / 128, S / 128, NH), 256, SMEM>>>(
        S, S, HD,
        qhi, qlo, HD, (long long)S * HD,
        khi, klo, HD, (long long)S * HD, GRP,
        sc, S, (long long)S * S);

    // 4. Softmax -> bf16 hi/lo probs
    softmax_kernel<<<dim3(S, NH), 256>>>(sc, phi, plo);

    // 5. PV: per Q-head [S, HD], K capped at diagonal
    mma_gemm<false, true><<<dim3(1, S / 128, NH), 256, SMEM>>>(
        S, HD, S,
        phi, plo, S, (long long)S * S,
        vthi, vtlo, S, (long long)HD * S, GRP,
        o, HID, HD);

    // 5b. attention out -> hi/lo
    convert_kernel<<<(S * HID) / 256, 256>>>(o, ohi, olo, S * HID);

    // 6. Output projection
    mma_gemm<false, false><<<dim3(HID / 128, S / 128, 1), 256, SMEM>>>(
        S, HID, HID, ohi, olo, HID, 0, wohi, wolo, HID, 0, 1, proj, HID, 0);

    // 7. Final RMSNorm
    final_norm_kernel<<<S, 256>>>(proj, lsc, out);
}

// round 4
// speedup vs baseline: 2.8571x; 1.1289x over previous
#include <cuda_runtime.h>
#include <cuda_bf16.h>
#include <math.h>
#include <stdint.h>

// Problem constants
#define S 2048
#define HID 2048
#define NH 16
#define NKV 4
#define HD 128
#define GRP (NH / NKV)
#define EPS 1e-6f
#define NQKV 3072  // NH*HD + 2*NKV*HD

typedef __nv_bfloat16 bf16;

// ---------------------------------------------------------------------------
// Scratch (device globals; allocation is forbidden)
// ---------------------------------------------------------------------------
__device__ float g_qkv[S * NQKV];                 // 24 MB  fused QKV proj out
__device__ bf16  g_xhi[S * HID], g_xlo[S * HID];
__device__ bf16  g_wqkvT_hi[NQKV * HID], g_wqkvT_lo[NQKV * HID];
__device__ bf16  g_woT_hi[HID * HID], g_woT_lo[HID * HID];
__device__ bf16  g_qhi[NH * S * HD], g_qlo[NH * S * HD];
__device__ bf16  g_khi[NKV * S * HD], g_klo[NKV * S * HD];
__device__ bf16  g_vthi[NKV * HD * S], g_vtlo[NKV * HD * S];
__device__ bf16  g_ohi[S * HID], g_olo[S * HID];  // attention out (hi/lo)
__device__ float g_proj[S * HID];                 // pre-final-norm

// ---------------------------------------------------------------------------
// PTX helpers (sm_80+ PTX only — legal under compute_103)
// ---------------------------------------------------------------------------
__device__ __forceinline__ uint32_t smem_u32(const void* p) {
    uint32_t a;
    asm("{ .reg .u64 t; cvta.to.shared.u64 t, %1; cvt.u32.u64 %0, t; }"
        : "=r"(a) : "l"(p));
    return a;
}

#define CP_ASYNC16(dst, src) \
    asm volatile("cp.async.cg.shared.global [%0], [%1], 16;" \
        :: "r"(dst), "l"(src))
#define CP_COMMIT() asm volatile("cp.async.commit_group;" ::: "memory")
#define CP_WAIT0() asm volatile("cp.async.wait_group 0;" ::: "memory")
#define CP_WAIT1() asm volatile("cp.async.wait_group 1;" ::: "memory")
#define CP_WAIT2() asm volatile("cp.async.wait_group 2;" ::: "memory")

#define LDSM_X4(r0, r1, r2, r3, addr) \
    asm volatile("ldmatrix.sync.aligned.m8n8.x4.shared.b16 {%0,%1,%2,%3}, [%4];" \
        : "=r"(r0), "=r"(r1), "=r"(r2), "=r"(r3) : "r"(addr))

#define MMA_BF16(d, a, b0, b1) \
    asm volatile("mma.sync.aligned.m16n8k16.row.col.f32.bf16.bf16.f32 " \
        "{%0,%1,%2,%3}, {%4,%5,%6,%7}, {%8,%9}, {%0,%1,%2,%3};" \
        : "+f"((d)[0]), "+f"((d)[1]), "+f"((d)[2]), "+f"((d)[3]) \
        : "r"((a)[0]), "r"((a)[1]), "r"((a)[2]), "r"((a)[3]), \
          "r"(b0), "r"(b1))

__device__ __forceinline__ void split_bf16(float v, bf16& h, bf16& l) {
    h = __float2bfloat16(v);
    l = __float2bfloat16(v - __bfloat162float(h));
}

__device__ __forceinline__ uint32_t pack_split(float v0, float v1, uint32_t& lo) {
    bf16 h0, l0, h1, l1;
    split_bf16(v0, h0, l0);
    split_bf16(v1, h1, l1);
    lo = (uint32_t)__bfloat16_as_ushort(l0) |
         ((uint32_t)__bfloat16_as_ushort(l1) << 16);
    return (uint32_t)__bfloat16_as_ushort(h0) |
           ((uint32_t)__bfloat16_as_ushort(h1) << 16);
}

// ---------------------------------------------------------------------------
// Split-bf16 GEMM: C[M,N] = A[M,K] @ B[N,K]^T. 3-stage cp.async pipeline,
// BM=BN=128, BK=64, 256 thr (8 warps, warp tile 32x64), swizzled 128B rows.
// ---------------------------------------------------------------------------
__global__ __launch_bounds__(256, 1) void mma_gemm(
    int M, int N, int K,
    const bf16* __restrict__ Ahi, const bf16* __restrict__ Alo, int lda,
    const bf16* __restrict__ Bhi, const bf16* __restrict__ Blo, int ldb,
    float* __restrict__ C, int ldc)
{
    constexpr int BK = 64;
    constexpr int TILE_B = 128 * BK * 2;    // 16 KB per (hi|lo) subtile
    constexpr int STAGE = 4 * TILE_B;       // 64 KB

    const int m0 = blockIdx.y * 128;
    const int n0 = blockIdx.x * 128;
    const int nIter = K / BK;

    extern __shared__ char smem[];
    const uint32_t sbase = smem_u32(smem);

    const int tid  = threadIdx.x;
    const int wid  = tid >> 5;
    const int lane = tid & 31;
    const int wm   = wid >> 1;
    const int wn   = wid & 1;

    auto load_stage = [&](int st, int k0) {
        const uint32_t base = sbase + st * STAGE;
#pragma unroll
        for (int t = 0; t < 4; t++) {
            int idx = tid + t * 256;
            int r = idx >> 3;
            int c = idx & 7;
            uint32_t soff = (uint32_t)(r * 128 + ((c ^ (r & 7)) << 4));
            long long ga = (long long)(m0 + r) * lda + k0 + c * 8;
            long long gb = (long long)(n0 + r) * ldb + k0 + c * 8;
            CP_ASYNC16(base + soff,              (const char*)(Ahi + ga));
            CP_ASYNC16(base + TILE_B + soff,     (const char*)(Alo + ga));
            CP_ASYNC16(base + 2 * TILE_B + soff, (const char*)(Bhi + gb));
            CP_ASYNC16(base + 3 * TILE_B + soff, (const char*)(Blo + gb));
        }
        CP_COMMIT();
    };

    const int lrow = lane & 15;
    const int lsel = lane >> 4;
    int arow[2], brow[4];
#pragma unroll
    for (int mt = 0; mt < 2; mt++) arow[mt] = wm * 32 + mt * 16 + lrow;
#pragma unroll
    for (int g = 0; g < 4; g++)    brow[g] = wn * 64 + g * 16 + lrow;

    float acc[2][8][4];
#pragma unroll
    for (int mt = 0; mt < 2; mt++)
#pragma unroll
        for (int j = 0; j < 8; j++)
#pragma unroll
            for (int e = 0; e < 4; e++) acc[mt][j][e] = 0.0f;

    load_stage(0, 0);
    if (nIter > 1) load_stage(1, BK);

    for (int it = 0; it < nIter; it++) {
        if (it + 2 < nIter) { load_stage((it + 2) % 3, (it + 2) * BK); CP_WAIT2(); }
        else if (it + 1 < nIter) { CP_WAIT1(); }
        else { CP_WAIT0(); }
        __syncthreads();

        const uint32_t base = sbase + (it % 3) * STAGE;
#pragma unroll
        for (int ks = 0; ks < 4; ks++) {
            const int chunk = ks * 2 + lsel;
            uint32_t ah[2][4], al[2][4], bh[4][4], bl[4][4];
#pragma unroll
            for (int mt = 0; mt < 2; mt++) {
                uint32_t off = (uint32_t)(arow[mt] * 128 +
                               ((chunk ^ (arow[mt] & 7)) << 4));
                LDSM_X4(ah[mt][0], ah[mt][1], ah[mt][2], ah[mt][3], base + off);
                LDSM_X4(al[mt][0], al[mt][1], al[mt][2], al[mt][3],
                        base + TILE_B + off);
            }
#pragma unroll
            for (int g = 0; g < 4; g++) {
                uint32_t off = (uint32_t)(brow[g] * 128 +
                               ((chunk ^ (brow[g] & 7)) << 4));
                LDSM_X4(bh[g][0], bh[g][1], bh[g][2], bh[g][3],
                        base + 2 * TILE_B + off);
                LDSM_X4(bl[g][0], bl[g][1], bl[g][2], bl[g][3],
                        base + 3 * TILE_B + off);
            }
#pragma unroll
            for (int mt = 0; mt < 2; mt++)
#pragma unroll
                for (int j = 0; j < 8; j++) {
                    int g = j >> 1, o = j & 1;
                    MMA_BF16(acc[mt][j], ah[mt], bh[g][o], bh[g][2 + o]);
                    MMA_BF16(acc[mt][j], ah[mt], bl[g][o], bl[g][2 + o]);
                    MMA_BF16(acc[mt][j], al[mt], bh[g][o], bh[g][2 + o]);
                }
        }
        __syncthreads();
    }

    const int er = lane >> 2;
    const int ec = (lane & 3) * 2;
#pragma unroll
    for (int mt = 0; mt < 2; mt++) {
        int r0 = m0 + wm * 32 + mt * 16 + er;
#pragma unroll
        for (int j = 0; j < 8; j++) {
            int col = n0 + wn * 64 + j * 8 + ec;
            *reinterpret_cast<float2*>(C + (long long)r0 * ldc + col) =
                make_float2(acc[mt][j][0], acc[mt][j][1]);
            *reinterpret_cast<float2*>(C + (long long)(r0 + 8) * ldc + col) =
                make_float2(acc[mt][j][2], acc[mt][j][3]);
        }
    }
}

// ---------------------------------------------------------------------------
// Fused flash attention: per CTA one head x one 128-row Q tile.
// 8 warps x 16 rows. KV tiles of 64, double-buffered cp.async.
// Online softmax; P->PV uses acc->A-fragment register identity (no shuffles).
// Writes attention out directly as bf16 hi/lo.
// ---------------------------------------------------------------------------
__global__ __launch_bounds__(256, 1) void flash_kernel(
    const bf16* __restrict__ qhi, const bf16* __restrict__ qlo,
    const bf16* __restrict__ khi, const bf16* __restrict__ klo,
    const bf16* __restrict__ vthi, const bf16* __restrict__ vtlo,
    bf16* __restrict__ ohi, bf16* __restrict__ olo)
{
    constexpr int BQ = 128, BKV = 64;
    constexpr int QB = 2 * BQ * HD * 2;        // 64 KB (Q hi + lo)
    constexpr int KSUB = BKV * 64 * 2;         // 8 KB per 64-k subtile
    constexpr int STAGE = 4 * 16384;           // KHI,KLO,VHI,VLO = 64 KB
    const float SCALE = 0.08838834764831845f;  // 1/sqrt(128)

    const int h   = blockIdx.y;
    const int qt  = gridDim.x - 1 - blockIdx.x;  // largest m0 first
    const int m0  = qt * BQ;
    const int kvh = h / GRP;
    const int jn  = m0 / BKV + 2;

    const bf16* qhi_h = qhi + (long long)h * S * HD;
    const bf16* qlo_h = qlo + (long long)h * S * HD;
    const bf16* khi_h = khi + (long long)kvh * S * HD;
    const bf16* klo_h = klo + (long long)kvh * S * HD;
    const bf16* vthi_h = vthi + (long long)kvh * HD * S;
    const bf16* vtlo_h = vtlo + (long long)kvh * HD * S;

    extern __shared__ char smem[];
    const uint32_t sbase = smem_u32(smem);

    const int tid  = threadIdx.x;
    const int w    = tid >> 5;
    const int lane = tid & 31;
    const int lrow = lane & 15;
    const int lsel = lane >> 4;

    // ---- loaders ----
    auto load_q = [&]() {
#pragma unroll
        for (int t = 0; t < 8; t++) {
            int idx = tid + t * 256;            // [0, 2048)
            int kc = idx >> 10, rem = idx & 1023;
            int r = rem >> 3, c = rem & 7;
            uint32_t soff = (uint32_t)(kc * 16384 + r * 128 +
                                       ((c ^ (r & 7)) << 4));
            long long g = (long long)(m0 + r) * HD + kc * 64 + c * 8;
            CP_ASYNC16(sbase + soff,         (const char*)(qhi_h + g));
            CP_ASYNC16(sbase + 32768 + soff, (const char*)(qlo_h + g));
        }
    };
    auto load_stage = [&](int st, int kv0) {
        const uint32_t base = sbase + QB + st * STAGE;
#pragma unroll
        for (int t = 0; t < 4; t++) {           // K tiles
            int idx = tid + t * 256;            // [0, 1024)
            int kc = idx >> 9, rem = idx & 511;
            int r = rem >> 3, c = rem & 7;
            uint32_t soff = (uint32_t)(kc * KSUB + r * 128 +
                                       ((c ^ (r & 7)) << 4));
            long long g = (long long)(kv0 + r) * HD + kc * 64 + c * 8;
            CP_ASYNC16(base + soff,         (const char*)(khi_h + g));
            CP_ASYNC16(base + 16384 + soff, (const char*)(klo_h + g));
        }
#pragma unroll
        for (int t = 0; t < 4; t++) {           // V^T tiles
            int idx = tid + t * 256;
            int r = idx >> 3, c = idx & 7;
            uint32_t soff = (uint32_t)(r * 128 + ((c ^ (r & 7)) << 4));
            long long g = (long long)r * S + kv0 + c * 8;
            CP_ASYNC16(base + 32768 + soff, (const char*)(vthi_h + g));
            CP_ASYNC16(base + 49152 + soff, (const char*)(vtlo_h + g));
        }
        CP_COMMIT();
    };

    load_q();
    load_stage(0, 0);
    CP_COMMIT();                       // group 0 = Q + stage0
    load_stage(1, BKV);                // group 1 = stage1 (jn >= 2 always)

    CP_WAIT1();
    __syncthreads();

    // ---- Q fragments (held in registers for the whole kernel) ----
    uint32_t qh[8][4], ql[8][4];
    {
        int row = w * 16 + lrow;
#pragma unroll
        for (int kchunk = 0; kchunk < 8; kchunk++) {
            int kc = kchunk >> 2, cc = kchunk & 3;
            int chunk = cc * 2 + lsel;
            uint32_t off = (uint32_t)(kc * 16384 + row * 128 +
                                      ((chunk ^ (row & 7)) << 4));
            LDSM_X4(qh[kchunk][0], qh[kchunk][1], qh[kchunk][2], qh[kchunk][3],
                    sbase + off);
            LDSM_X4(ql[kchunk][0], ql[kchunk][1], ql[kchunk][2], ql[kchunk][3],
                    sbase + 32768 + off);
        }
    }

    float oacc[16][4];
#pragma unroll
    for (int nt = 0; nt < 16; nt++)
#pragma unroll
        for (int e = 0; e < 4; e++) oacc[nt][e] = 0.0f;
    float mrow[2] = {-1e30f, -1e30f};
    float lsum[2] = {0.0f, 0.0f};

    const int rg0 = m0 + w * 16 + (lane >> 2);  // global row (e 0,1)
    const int cb  = (lane & 3) * 2;             // col base within n8

    for (int j = 0; j < jn; j++) {
        const int kv0 = j * BKV;
        const bool masked = (kv0 + BKV > m0);

        if (j + 1 < jn) CP_WAIT1(); else CP_WAIT0();
        __syncthreads();

        const uint32_t base = sbase + QB + (j & 1) * STAGE;

        // ---- S = Q K^T ----
        float s[8][4];
#pragma unroll
        for (int nt = 0; nt < 8; nt++)
#pragma unroll
            for (int e = 0; e < 4; e++) s[nt][e] = 0.0f;

#pragma unroll
        for (int kchunk = 0; kchunk < 8; kchunk++) {
            int kc = kchunk >> 2, cc = kchunk & 3;
            int chunk = cc * 2 + lsel;
#pragma unroll
            for (int g = 0; g < 4; g++) {
                int row = g * 16 + lrow;
                uint32_t off = (uint32_t)(kc * KSUB + row * 128 +
                                          ((chunk ^ (row & 7)) << 4));
                uint32_t bh[4], bl[4];
                LDSM_X4(bh[0], bh[1], bh[2], bh[3], base + off);
                LDSM_X4(bl[0], bl[1], bl[2], bl[3], base + 16384 + off);
#pragma unroll
                for (int o = 0; o < 2; o++) {
                    int nt = g * 2 + o;
                    MMA_BF16(s[nt], qh[kchunk], bh[o], bh[2 + o]);
                    MMA_BF16(s[nt], qh[kchunk], bl[o], bl[2 + o]);
                    MMA_BF16(s[nt], ql[kchunk], bh[o], bh[2 + o]);
                }
            }
        }

        // ---- scale + causal mask ----
#pragma unroll
        for (int nt = 0; nt < 8; nt++)
#pragma unroll
            for (int e = 0; e < 4; e++) {
                float v = s[nt][e] * SCALE;
                if (masked) {
                    int col = kv0 + nt * 8 + cb + (e & 1);
                    int row = rg0 + ((e >> 1) << 3);
                    if (col > row) v = -1e30f;
                }
                s[nt][e] = v;
            }

        // ---- online softmax ----
        float mx0 = -1e30f, mx1 = -1e30f;
#pragma unroll
        for (int nt = 0; nt < 8; nt++) {
            mx0 = fmaxf(mx0, fmaxf(s[nt][0], s[nt][1]));
            mx1 = fmaxf(mx1, fmaxf(s[nt][2], s[nt][3]));
        }
        mx0 = fmaxf(mx0, __shfl_xor_sync(0xffffffffu, mx0, 1));
        mx0 = fmaxf(mx0, __shfl_xor_sync(0xffffffffu, mx0, 2));
        mx1 = fmaxf(mx1, __shfl_xor_sync(0xffffffffu, mx1, 1));
        mx1 = fmaxf(mx1, __shfl_xor_sync(0xffffffffu, mx1, 2));

        float mn0 = fmaxf(mrow[0], mx0);
        float mn1 = fmaxf(mrow[1], mx1);
        float a0 = __expf(mrow[0] - mn0);
        float a1 = __expf(mrow[1] - mn1);

        float sum0 = 0.0f, sum1 = 0.0f;
#pragma unroll
        for (int nt = 0; nt < 8; nt++) {
            s[nt][0] = __expf(s[nt][0] - mn0);
            s[nt][1] = __expf(s[nt][1] - mn0);
            s[nt][2] = __expf(s[nt][2] - mn1);
            s[nt][3] = __expf(s[nt][3] - mn1);
            sum0 += s[nt][0] + s[nt][1];
            sum1 += s[nt][2] + s[nt][3];
        }
        sum0 += __shfl_xor_sync(0xffffffffu, sum0, 1);
        sum0 += __shfl_xor_sync(0xffffffffu, sum0, 2);
        sum1 += __shfl_xor_sync(0xffffffffu, sum1, 1);
        sum1 += __shfl_xor_sync(0xffffffffu, sum1, 2);

        lsum[0] = lsum[0] * a0 + sum0;
        lsum[1] = lsum[1] * a1 + sum1;
        mrow[0] = mn0;
        mrow[1] = mn1;

#pragma unroll
        for (int nt = 0; nt < 16; nt++) {
            oacc[nt][0] *= a0; oacc[nt][1] *= a0;
            oacc[nt][2] *= a1; oacc[nt][3] *= a1;
        }

        // ---- O += P V  (P fragments from acc registers directly) ----
#pragma unroll
        for (int kc2 = 0; kc2 < 4; kc2++) {
            uint32_t ph[4], pl[4];
            ph[0] = pack_split(s[2 * kc2][0],     s[2 * kc2][1],     pl[0]);
            ph[1] = pack_split(s[2 * kc2][2],     s[2 * kc2][3],     pl[1]);
            ph[2] = pack_split(s[2 * kc2 + 1][0], s[2 * kc2 + 1][1], pl[2]);
            ph[3] = pack_split(s[2 * kc2 + 1][2], s[2 * kc2 + 1][3], pl[3]);
            int chunk = kc2 * 2 + lsel;
#pragma unroll
            for (int g = 0; g < 8; g++) {
                int row = g * 16 + lrow;
                uint32_t off = (uint32_t)(32768 + row * 128 +
                                          ((chunk ^ (row & 7)) << 4));
                uint32_t vh[4], vl[4];
                LDSM_X4(vh[0], vh[1], vh[2], vh[3], base + off);
                LDSM_X4(vl[0], vl[1], vl[2], vl[3], base + 16384 + off);
#pragma unroll
                for (int o = 0; o < 2; o++) {
                    int nt = g * 2 + o;
                    MMA_BF16(oacc[nt], ph, vh[o], vh[2 + o]);
                    MMA_BF16(oacc[nt], ph, vl[o], vl[2 + o]);
                    MMA_BF16(oacc[nt], pl, vh[o], vh[2 + o]);
                }
            }
        }

        __syncthreads();
        if (j + 2 < jn) load_stage(j & 1, (j + 2) * BKV);
    }

    // ---- epilogue: normalize and store bf16 hi/lo ----
    float inv0 = 1.0f / lsum[0];
    float inv1 = 1.0f / lsum[1];
    const long long r0 = (long long)rg0 * HID + h * HD;
    const long long r1 = r0 + 8LL * HID;
#pragma unroll
    for (int nt = 0; nt < 16; nt++) {
        int col = nt * 8 + cb;
        uint32_t lo;
        uint32_t hi = pack_split(oacc[nt][0] * inv0, oacc[nt][1] * inv0, lo);
        *reinterpret_cast<uint32_t*>(ohi + r0 + col) = hi;
        *reinterpret_cast<uint32_t*>(olo + r0 + col) = lo;
        hi = pack_split(oacc[nt][2] * inv1, oacc[nt][3] * inv1, lo);
        *reinterpret_cast<uint32_t*>(ohi + r1 + col) = hi;
        *reinterpret_cast<uint32_t*>(olo + r1 + col) = lo;
    }
}

// ---------------------------------------------------------------------------
// Elementwise fp32 -> bf16 (hi, lo)
// ---------------------------------------------------------------------------
__global__ __launch_bounds__(256) void convert_kernel(
    const float* __restrict__ in, bf16* __restrict__ hi,
    bf16* __restrict__ lo, int n)
{
    int idx = blockIdx.x * 256 + threadIdx.x;
    if (idx < n) {
        bf16 h, l;
        split_bf16(in[idx], h, l);
        hi[idx] = h; lo[idx] = l;
    }
}

// ---------------------------------------------------------------------------
// Transpose + convert: out[c][r] = split(in[r][c])
// ---------------------------------------------------------------------------
__global__ __launch_bounds__(256) void transpose_conv_kernel(
    const float* __restrict__ in, int ldi, long long sIn,
    bf16* __restrict__ ohi, bf16* __restrict__ olo, int ldo, long long sOut)
{
    __shared__ float t[32][33];
    const float* ip = in + (long long)blockIdx.z * sIn;
    bf16* oh = ohi + (long long)blockIdx.z * sOut;
    bf16* ol = olo + (long long)blockIdx.z * sOut;
    int c0 = blockIdx.x * 32, r0 = blockIdx.y * 32;
    int x = threadIdx.x, y = threadIdx.y;
#pragma unroll
    for (int i = 0; i < 32; i += 8)
        t[y + i][x] = ip[(long long)(r0 + y + i) * ldi + c0 + x];
    __syncthreads();
#pragma unroll
    for (int i = 0; i < 32; i += 8) {
        bf16 h, l;
        split_bf16(t[x][y + i], h, l);
        long long o = (long long)(c0 + y + i) * ldo + r0 + x;
        oh[o] = h; ol[o] = l;
    }
}

// ---------------------------------------------------------------------------
// Per-head RMSNorm + RoPE from fused QKV buffer -> head-major bf16 hi/lo.
// ---------------------------------------------------------------------------
__global__ __launch_bounds__(128) void norm_rope_kernel(
    const float* __restrict__ qkv,
    const float* __restrict__ cosT, const float* __restrict__ sinT,
    const float* __restrict__ qscale, const float* __restrict__ kscale,
    bf16* __restrict__ qhi, bf16* __restrict__ qlo,
    bf16* __restrict__ khi, bf16* __restrict__ klo)
{
    int s = blockIdx.x;
    int h = blockIdx.y;
    int d = threadIdx.x;

    const float* src;
    long long dsto;
    const float* sc;
    bf16 *dhi, *dlo;
    if (h < NH) {
        src  = qkv + (long long)s * NQKV + h * HD;
        dsto = ((long long)h * S + s) * HD;
        sc = qscale; dhi = qhi; dlo = qlo;
    } else {
        int hk = h - NH;
        src  = qkv + (long long)s * NQKV + HID + hk * HD;
        dsto = ((long long)hk * S + s) * HD;
        sc = kscale; dhi = khi; dlo = klo;
    }

    float x = src[d];
    float v = x * x;
#pragma unroll
    for (int o = 16; o > 0; o >>= 1) v += __shfl_xor_sync(0xffffffffu, v, o);
    __shared__ float red[4];
    if ((d & 31) == 0) red[d >> 5] = v;
    __syncthreads();
    float tot = red[0] + red[1] + red[2] + red[3];
    float r = rsqrtf(tot * (1.0f / HD) + EPS);

    __shared__ float xn[HD];
    float xv = x * r * sc[d];
    xn[d] = xv;
    __syncthreads();
    float other = (d < HD / 2) ? -xn[d + HD / 2] : xn[d - HD / 2];

    float c  = cosT[(long long)s * HD + d];
    float sn = sinT[(long long)s * HD + d];
    float outv = xv * c + other * sn;
    bf16 hh, ll;
    split_bf16(outv, hh, ll);
    dhi[dsto + d] = hh;
    dlo[dsto + d] = ll;
}

// ---------------------------------------------------------------------------
// Final RMSNorm over HID.
// ---------------------------------------------------------------------------
__global__ __launch_bounds__(256) void final_norm_kernel(
    const float* __restrict__ in, const float* __restrict__ scale,
    float* __restrict__ out)
{
    int s = blockIdx.x;
    int t = threadIdx.x;
    const float* row = in + (long long)s * HID;

    float loc[8];
    float ss = 0.0f;
#pragma unroll
    for (int c = 0; c < 8; c++) {
        float v = row[t + c * 256];
        loc[c] = v;
        ss += v * v;
    }
    __shared__ float red[8];
#pragma unroll
    for (int o = 16; o > 0; o >>= 1) ss += __shfl_xor_sync(0xffffffffu, ss, o);
    if ((t & 31) == 0) red[t >> 5] = ss;
    __syncthreads();
    if (t == 0) {
        float v = 0.0f;
        for (int w = 0; w < 8; w++) v += red[w];
        red[0] = v;
    }
    __syncthreads();
    float r = rsqrtf(red[0] * (1.0f / HID) + EPS);
#pragma unroll
    for (int c = 0; c < 8; c++)
        out[(long long)s * HID + t + c * 256] = loc[c] * r * scale[t + c * 256];
}

// ---------------------------------------------------------------------------
// Host launch
// ---------------------------------------------------------------------------
extern "C" void kernel_launch(void* const* d_in, const int* in_sizes, int n_in,
                              void* d_out, int out_size)
{
    const float* X    = (const float*)d_in[0];
    const float* cosT = (const float*)d_in[1];
    const float* sinT = (const float*)d_in[2];
    const float* Wq   = (const float*)d_in[3];
    const float* Wk   = (const float*)d_in[4];
    const float* Wv   = (const float*)d_in[5];
    const float* Wo   = (const float*)d_in[6];
    const float* qsc  = (const float*)d_in[7];
    const float* ksc  = (const float*)d_in[8];
    const float* lsc  = (const float*)d_in[9];
    float* out = (float*)d_out;

    float *qkv, *proj;
    bf16 *xhi, *xlo, *wqkvhi, *wqkvlo, *wohi, *wolo;
    bf16 *qhi, *qlo, *khi, *klo, *vthi, *vtlo, *ohi, *olo;
    cudaGetSymbolAddress((void**)&qkv,    g_qkv);
    cudaGetSymbolAddress((void**)&proj,   g_proj);
    cudaGetSymbolAddress((void**)&xhi,    g_xhi);
    cudaGetSymbolAddress((void**)&xlo,    g_xlo);
    cudaGetSymbolAddress((void**)&wqkvhi, g_wqkvT_hi);
    cudaGetSymbolAddress((void**)&wqkvlo, g_wqkvT_lo);
    cudaGetSymbolAddress((void**)&wohi,   g_woT_hi);
    cudaGetSymbolAddress((void**)&wolo,   g_woT_lo);
    cudaGetSymbolAddress((void**)&qhi,    g_qhi);
    cudaGetSymbolAddress((void**)&qlo,    g_qlo);
    cudaGetSymbolAddress((void**)&khi,    g_khi);
    cudaGetSymbolAddress((void**)&klo,    g_klo);
    cudaGetSymbolAddress((void**)&vthi,   g_vthi);
    cudaGetSymbolAddress((void**)&vtlo,   g_vtlo);
    cudaGetSymbolAddress((void**)&ohi,    g_ohi);
    cudaGetSymbolAddress((void**)&olo,    g_olo);

    const int SMEM_GEMM  = 3 * 4 * 128 * 64 * 2;               // 196608
    const int SMEM_FLASH = 2 * 128 * 128 * 2 + 2 * 4 * 16384;  // 196608
    cudaFuncSetAttribute(mma_gemm,
                         cudaFuncAttributeMaxDynamicSharedMemorySize, SMEM_GEMM);
    cudaFuncSetAttribute(flash_kernel,
                         cudaFuncAttributeMaxDynamicSharedMemorySize, SMEM_FLASH);

    // 0a. X -> hi/lo
    convert_kernel<<<(S * HID) / 256, 256>>>(X, xhi, xlo, S * HID);
    // 0b. Weights: transpose+convert (fused QKV) and Wo^T
    transpose_conv_kernel<<<dim3(HID / 32, HID / 32, 1), dim3(32, 8)>>>(
        Wq, HID, 0, wqkvhi, wqkvlo, HID, 0);
    transpose_conv_kernel<<<dim3((NKV * HD) / 32, HID / 32, 1), dim3(32, 8)>>>(
        Wk, NKV * HD, 0, wqkvhi + (long long)HID * HID,
        wqkvlo + (long long)HID * HID, HID, 0);
    transpose_conv_kernel<<<dim3((NKV * HD) / 32, HID / 32, 1), dim3(32, 8)>>>(
        Wv, NKV * HD, 0, wqkvhi + (long long)(HID + NKV * HD) * HID,
        wqkvlo + (long long)(HID + NKV * HD) * HID, HID, 0);
    transpose_conv_kernel<<<dim3(HID / 32, HID / 32, 1), dim3(32, 8)>>>(
        Wo, HID, 0, wohi, wolo, HID, 0);

    // 1. Fused QKV projection
    mma_gemm<<<dim3(NQKV / 128, S / 128), 256, SMEM_GEMM>>>(
        S, NQKV, HID, xhi, xlo, HID, wqkvhi, wqkvlo, HID, qkv, NQKV);

    // 2. Per-head RMSNorm + RoPE -> head-major bf16 hi/lo
    norm_rope_kernel<<<dim3(S, NH + NKV), 128>>>(
        qkv, cosT, sinT, qsc, ksc, qhi, qlo, khi, klo);

    // 2b. V^T per kv head: [kv][d][s]
    transpose_conv_kernel<<<dim3(HD / 32, S / 32, NKV), dim3(32, 8)>>>(
        qkv + HID + NKV * HD, NQKV, HD, vthi, vtlo, S, (long long)HD * S);

    // 3-5. Fused flash attention (scores + softmax + PV), writes hi/lo out
    flash_kernel<<<dim3(S / 128, NH), 256, SMEM_FLASH>>>(
        qhi, qlo, khi, klo, vthi, vtlo, ohi, olo);

    // 6. Output projection
    mma_gemm<<<dim3(HID / 128, S / 128), 256, SMEM_GEMM>>>(
        S, HID, HID, ohi, olo, HID, wohi, wolo, HID, proj, HID);

    // 7. Final RMSNorm
    final_norm_kernel<<<S, 256>>>(proj, lsc, out);
}